// round 1
// baseline (speedup 1.0000x reference)
#include <cuda_runtime.h>
#include <mma.h>
#include <cstdint>

using namespace nvcuda;

#define NPOL 20000
#define NSTK 10000
#define EDG  400000
#define HID  512
#define NC   3

// ---------------- device scratch (no allocations allowed) ----------------
__device__ float g_hp   [(size_t)NPOL * HID];
__device__ float g_hs   [(size_t)NSTK * HID];
__device__ float g_hp1  [(size_t)NPOL * HID];
__device__ float g_hs1  [(size_t)NSTK * HID];
__device__ float g_meanp[(size_t)NPOL * HID];
__device__ float g_means[(size_t)NSTK * HID];
__device__ float g_A    [(size_t)NPOL * HID];
__device__ float g_B    [(size_t)NSTK * HID];

__device__ int g_cnt_ps[NSTK];
__device__ int g_off_ps[NSTK + 1];
__device__ int g_cur_ps[NSTK];
__device__ int g_src_ps[EDG];

__device__ int g_cnt_sp[NPOL];
__device__ int g_off_sp[NPOL + 1];
__device__ int g_cur_sp[NPOL];
__device__ int g_src_sp[EDG];

// ---------------- CSR build ----------------
__global__ void zero2_kernel(int* a, int na, int* b, int nb) {
    int i  = blockIdx.x * blockDim.x + threadIdx.x;
    int st = gridDim.x * blockDim.x;
    for (int j = i; j < na; j += st) a[j] = 0;
    for (int j = i; j < nb; j += st) b[j] = 0;
}

__global__ void histo2_kernel(const int* __restrict__ d0, int* c0,
                              const int* __restrict__ d1, int* c1, int n) {
    int i  = blockIdx.x * blockDim.x + threadIdx.x;
    int st = gridDim.x * blockDim.x;
    for (int e = i; e < n; e += st) {
        atomicAdd(&c0[d0[e]], 1);
        atomicAdd(&c1[d1[e]], 1);
    }
}

// one block per relation: exclusive scan of counts -> off, cur
__global__ __launch_bounds__(1024) void exscan2_kernel(
    const int* __restrict__ cnt0, int n0, int* off0, int* cur0,
    const int* __restrict__ cnt1, int n1, int* off1, int* cur1) {
    const int* cnt = blockIdx.x ? cnt1 : cnt0;
    int  n   = blockIdx.x ? n1 : n0;
    int* off = blockIdx.x ? off1 : off0;
    int* cur = blockIdx.x ? cur1 : cur0;

    __shared__ int buf[1024];
    __shared__ int s_carry;
    int tid = threadIdx.x;
    if (tid == 0) s_carry = 0;
    __syncthreads();

    for (int base = 0; base < n; base += 1024) {
        int i = base + tid;
        int v = (i < n) ? cnt[i] : 0;
        buf[tid] = v;
        __syncthreads();
        #pragma unroll
        for (int o = 1; o < 1024; o <<= 1) {
            int t = (tid >= o) ? buf[tid - o] : 0;
            __syncthreads();
            buf[tid] += t;
            __syncthreads();
        }
        int incl  = buf[tid];
        int total = buf[1023];
        if (i < n) {
            int ex = s_carry + incl - v;
            off[i] = ex;
            cur[i] = ex;
        }
        __syncthreads();
        if (tid == 0) s_carry += total;
        __syncthreads();
    }
    if (tid == 0) off[n] = s_carry;
}

__global__ void scatter2_kernel(const int* __restrict__ s0, const int* __restrict__ dd0,
                                int* cur0, int* o0,
                                const int* __restrict__ s1, const int* __restrict__ dd1,
                                int* cur1, int* o1, int n) {
    int i  = blockIdx.x * blockDim.x + threadIdx.x;
    int st = gridDim.x * blockDim.x;
    for (int e = i; e < n; e += st) {
        int p0 = atomicAdd(&cur0[dd0[e]], 1);
        o0[p0] = s0[e];
        int p1 = atomicAdd(&cur1[dd1[e]], 1);
        o1[p1] = s1[e];
    }
}

// ---------------- mean aggregation over CSR ----------------
// one block (128 threads) per destination row; each thread owns 4 columns (float4)
__global__ __launch_bounds__(128) void agg_mean_kernel(
    const float* __restrict__ X, const int* __restrict__ off,
    const int* __restrict__ srcs, float* __restrict__ out) {
    int d   = blockIdx.x;
    int tid = threadIdx.x;
    int beg = off[d];
    int end = off[d + 1];

    __shared__ int sIdx[128];
    float4 acc = make_float4(0.f, 0.f, 0.f, 0.f);

    for (int cb = beg; cb < end; cb += 128) {
        int m = min(128, end - cb);
        if (tid < m) sIdx[tid] = srcs[cb + tid];
        __syncthreads();
        for (int j = 0; j < m; j++) {
            const float4* row = reinterpret_cast<const float4*>(X + (size_t)sIdx[j] * HID);
            float4 v = row[tid];
            acc.x += v.x; acc.y += v.y; acc.z += v.z; acc.w += v.w;
        }
        __syncthreads();
    }
    float inv = (end > beg) ? 1.0f / (float)(end - beg) : 0.0f;
    float4 r  = make_float4(acc.x * inv, acc.y * inv, acc.z * inv, acc.w * inv);
    reinterpret_cast<float4*>(out + (size_t)d * HID)[tid] = r;
}

// ---------------- tf32 WMMA GEMM: C[M,512] = act( sum_p Xp[M,K] @ Wp[K,512] + bias ) ----
// BM=64, BN=64, BK=16, 128 threads (4 warps, each a 32x32 sub-tile of 2x2 wmma frags)
#define BM 64
#define BN 64
#define BK 16

__global__ __launch_bounds__(128) void gemm_tf32_kernel(
    const float* __restrict__ X0, const float* __restrict__ W0,
    const float* __restrict__ X1, const float* __restrict__ W1,
    const float* __restrict__ bias, float* __restrict__ C,
    int M, int K, int npair, int dorelu) {
    // pads chosen so every wmma fragment base stays 32B-aligned (multiples of 8 floats)
    __shared__ float Xs[BM][BK];        // ld 16
    __shared__ float Ws[BK][BN + 8];    // ld 72
    __shared__ float Cs[BM][BN + 8];    // ld 72

    int row0 = blockIdx.x * BM;
    int n0   = blockIdx.y * BN;
    int tid  = threadIdx.x;
    int warp = tid >> 5;
    int wm   = warp >> 1;   // 0..1
    int wn   = warp & 1;    // 0..1

    wmma::fragment<wmma::accumulator, 16, 16, 8, float> acc[2][2];
    #pragma unroll
    for (int i = 0; i < 2; i++)
        #pragma unroll
        for (int j = 0; j < 2; j++)
            wmma::fill_fragment(acc[i][j], 0.0f);

    for (int p = 0; p < npair; p++) {
        const float* X = p ? X1 : X0;
        const float* W = p ? W1 : W0;
        for (int k0 = 0; k0 < K; k0 += BK) {
            // load X tile 64x16
            {
                int r = tid >> 2;          // 0..31
                int c = (tid & 3) * 4;     // 0..12
                #pragma unroll
                for (int rr = 0; rr < 2; rr++) {
                    int row = row0 + r + rr * 32;
                    float4 v = make_float4(0.f, 0.f, 0.f, 0.f);
                    if (row < M)
                        v = *reinterpret_cast<const float4*>(X + (size_t)row * K + k0 + c);
                    *reinterpret_cast<float4*>(&Xs[r + rr * 32][c]) = v;
                }
            }
            // load W tile 16x64
            {
                int r = tid >> 4;          // 0..7
                int c = (tid & 15) * 4;    // 0..60
                #pragma unroll
                for (int rr = 0; rr < 2; rr++) {
                    float4 v = *reinterpret_cast<const float4*>(
                        W + (size_t)(k0 + r + rr * 8) * HID + n0 + c);
                    *reinterpret_cast<float4*>(&Ws[r + rr * 8][c]) = v;
                }
            }
            __syncthreads();

            #pragma unroll
            for (int kk = 0; kk < BK; kk += 8) {
                wmma::fragment<wmma::matrix_a, 16, 16, 8, wmma::precision::tf32, wmma::row_major> a[2];
                wmma::fragment<wmma::matrix_b, 16, 16, 8, wmma::precision::tf32, wmma::row_major> b[2];
                #pragma unroll
                for (int i = 0; i < 2; i++) {
                    wmma::load_matrix_sync(a[i], &Xs[wm * 32 + i * 16][kk], BK);
                    #pragma unroll
                    for (int t = 0; t < a[i].num_elements; t++)
                        a[i].x[t] = wmma::__float_to_tf32(a[i].x[t]);
                }
                #pragma unroll
                for (int j = 0; j < 2; j++) {
                    wmma::load_matrix_sync(b[j], &Ws[kk][wn * 32 + j * 16], BN + 8);
                    #pragma unroll
                    for (int t = 0; t < b[j].num_elements; t++)
                        b[j].x[t] = wmma::__float_to_tf32(b[j].x[t]);
                }
                #pragma unroll
                for (int i = 0; i < 2; i++)
                    #pragma unroll
                    for (int j = 0; j < 2; j++)
                        wmma::mma_sync(acc[i][j], a[i], b[j], acc[i][j]);
            }
            __syncthreads();
        }
    }

    #pragma unroll
    for (int i = 0; i < 2; i++)
        #pragma unroll
        for (int j = 0; j < 2; j++)
            wmma::store_matrix_sync(&Cs[wm * 32 + i * 16][wn * 32 + j * 16],
                                    acc[i][j], BN + 8, wmma::mem_row_major);
    __syncthreads();

    for (int idx = tid; idx < BM * BN; idx += 128) {
        int r = idx >> 6;
        int c = idx & 63;
        int row = row0 + r;
        if (row < M) {
            float v = Cs[r][c];
            if (bias) v += bias[n0 + c];
            if (dorelu) v = fmaxf(v, 0.f);
            C[(size_t)row * HID + n0 + c] = v;
        }
    }
}

// ---------------- fused per-edge decoder ----------------
// out[e,:] = relu(A[r] + B[c] + a0*w0 + a1*w1 + d1_b) @ d2_W + d2_b
__global__ __launch_bounds__(256) void edge_decode_kernel(
    const float* __restrict__ Aa, const float* __restrict__ Bb,
    const float* __restrict__ attr,
    const float* __restrict__ w0, const float* __restrict__ w1,
    const float* __restrict__ b1,
    const float* __restrict__ d2W, const float* __restrict__ d2b,
    const int* __restrict__ erow, const int* __restrict__ ecol,
    float* __restrict__ out) {
    __shared__ float4 s_w0[128], s_w1[128], s_b[128], s_d0[128], s_d1[128], s_d2[128];
    int tid = threadIdx.x;
    for (int i = tid; i < HID; i += 256) {
        ((float*)s_w0)[i] = w0[i];
        ((float*)s_w1)[i] = w1[i];
        ((float*)s_b)[i]  = b1[i];
        ((float*)s_d0)[i] = d2W[i * 3 + 0];
        ((float*)s_d1)[i] = d2W[i * 3 + 1];
        ((float*)s_d2)[i] = d2W[i * 3 + 2];
    }
    __syncthreads();
    float db0 = d2b[0], db1 = d2b[1], db2 = d2b[2];
    int lane = tid & 31;
    int warp = tid >> 5;

    for (int e = blockIdx.x * 8 + warp; e < EDG; e += gridDim.x * 8) {
        int r = erow[e];
        int c = ecol[e];
        float a0 = attr[2 * e];
        float a1 = attr[2 * e + 1];
        const float4* A4 = reinterpret_cast<const float4*>(Aa + (size_t)r * HID);
        const float4* B4 = reinterpret_cast<const float4*>(Bb + (size_t)c * HID);
        float s0 = 0.f, s1 = 0.f, s2 = 0.f;
        #pragma unroll
        for (int k = 0; k < 4; k++) {
            int q = k * 32 + lane;
            float4 va = A4[q], vb = B4[q];
            float4 vw0 = s_w0[q], vw1 = s_w1[q], vbb = s_b[q];
            float4 v0 = s_d0[q], v1 = s_d1[q], v2 = s_d2[q];
            float h;
            h = fmaxf(va.x + vb.x + a0 * vw0.x + a1 * vw1.x + vbb.x, 0.f);
            s0 += h * v0.x; s1 += h * v1.x; s2 += h * v2.x;
            h = fmaxf(va.y + vb.y + a0 * vw0.y + a1 * vw1.y + vbb.y, 0.f);
            s0 += h * v0.y; s1 += h * v1.y; s2 += h * v2.y;
            h = fmaxf(va.z + vb.z + a0 * vw0.z + a1 * vw1.z + vbb.z, 0.f);
            s0 += h * v0.z; s1 += h * v1.z; s2 += h * v2.z;
            h = fmaxf(va.w + vb.w + a0 * vw0.w + a1 * vw1.w + vbb.w, 0.f);
            s0 += h * v0.w; s1 += h * v1.w; s2 += h * v2.w;
        }
        #pragma unroll
        for (int o = 16; o > 0; o >>= 1) {
            s0 += __shfl_xor_sync(0xffffffffu, s0, o);
            s1 += __shfl_xor_sync(0xffffffffu, s1, o);
            s2 += __shfl_xor_sync(0xffffffffu, s2, o);
        }
        if (lane == 0) {
            out[(size_t)e * 3 + 0] = s0 + db0;
            out[(size_t)e * 3 + 1] = s1 + db1;
            out[(size_t)e * 3 + 2] = s2 + db2;
        }
    }
}

// ---------------- host launch ----------------
extern "C" void kernel_launch(void* const* d_in, const int* in_sizes, int n_in,
                              void* d_out, int out_size) {
    (void)in_sizes; (void)n_in; (void)out_size;

    const float* x_pol = (const float*)d_in[0];
    const float* x_stk = (const float*)d_in[1];
    const float* attr  = (const float*)d_in[2];
    const float* Wp    = (const float*)d_in[3];
    const float* bp    = (const float*)d_in[4];
    const float* Ws    = (const float*)d_in[5];
    const float* bs    = (const float*)d_in[6];
    const float* c1_ps_Wl = (const float*)d_in[7];
    const float* c1_ps_bl = (const float*)d_in[8];
    const float* c1_ps_Wr = (const float*)d_in[9];
    const float* c1_sp_Wl = (const float*)d_in[10];
    const float* c1_sp_bl = (const float*)d_in[11];
    const float* c1_sp_Wr = (const float*)d_in[12];
    const float* c2_ps_Wl = (const float*)d_in[13];
    const float* c2_ps_bl = (const float*)d_in[14];
    const float* c2_ps_Wr = (const float*)d_in[15];
    const float* c2_sp_Wl = (const float*)d_in[16];
    const float* c2_sp_bl = (const float*)d_in[17];
    const float* c2_sp_Wr = (const float*)d_in[18];
    const float* d1_W  = (const float*)d_in[19];   // [1026, 512] row-major
    const float* d1_b  = (const float*)d_in[20];
    const float* d2_W  = (const float*)d_in[21];   // [512, 3]
    const float* d2_b  = (const float*)d_in[22];
    const int* eps_src = (const int*)d_in[23];
    const int* eps_dst = (const int*)d_in[24];
    const int* esp_src = (const int*)d_in[25];
    const int* esp_dst = (const int*)d_in[26];
    const int* trow    = (const int*)d_in[27];
    const int* tcol    = (const int*)d_in[28];
    float* out = (float*)d_out;

    void* p;
    cudaGetSymbolAddress(&p, g_hp);     float* hp    = (float*)p;
    cudaGetSymbolAddress(&p, g_hs);     float* hs    = (float*)p;
    cudaGetSymbolAddress(&p, g_hp1);    float* hp1   = (float*)p;
    cudaGetSymbolAddress(&p, g_hs1);    float* hs1   = (float*)p;
    cudaGetSymbolAddress(&p, g_meanp);  float* meanp = (float*)p;
    cudaGetSymbolAddress(&p, g_means);  float* means = (float*)p;
    cudaGetSymbolAddress(&p, g_A);      float* Abuf  = (float*)p;
    cudaGetSymbolAddress(&p, g_B);      float* Bbuf  = (float*)p;
    cudaGetSymbolAddress(&p, g_cnt_ps); int* cnt_ps = (int*)p;
    cudaGetSymbolAddress(&p, g_off_ps); int* off_ps = (int*)p;
    cudaGetSymbolAddress(&p, g_cur_ps); int* cur_ps = (int*)p;
    cudaGetSymbolAddress(&p, g_src_ps); int* src_ps = (int*)p;
    cudaGetSymbolAddress(&p, g_cnt_sp); int* cnt_sp = (int*)p;
    cudaGetSymbolAddress(&p, g_off_sp); int* off_sp = (int*)p;
    cudaGetSymbolAddress(&p, g_cur_sp); int* cur_sp = (int*)p;
    cudaGetSymbolAddress(&p, g_src_sp); int* src_sp = (int*)p;

    // ---- CSR build (both relations) ----
    zero2_kernel<<<64, 256>>>(cnt_ps, NSTK, cnt_sp, NPOL);
    histo2_kernel<<<400, 256>>>(eps_dst, cnt_ps, esp_dst, cnt_sp, EDG);
    exscan2_kernel<<<2, 1024>>>(cnt_ps, NSTK, off_ps, cur_ps,
                                cnt_sp, NPOL, off_sp, cur_sp);
    scatter2_kernel<<<400, 256>>>(eps_src, eps_dst, cur_ps, src_ps,
                                  esp_src, esp_dst, cur_sp, src_sp, EDG);

    dim3 gP((NPOL + BM - 1) / BM, HID / BN);
    dim3 gS((NSTK + BM - 1) / BM, HID / BN);

    // ---- input projections ----
    gemm_tf32_kernel<<<gP, 128>>>(x_pol, Wp, nullptr, nullptr, bp, hp, NPOL, 64, 1, 1);
    gemm_tf32_kernel<<<gS, 128>>>(x_stk, Ws, nullptr, nullptr, bs, hs, NSTK, 64, 1, 1);

    // ---- conv1 ----
    agg_mean_kernel<<<NSTK, 128>>>(hp, off_ps, src_ps, means);
    agg_mean_kernel<<<NPOL, 128>>>(hs, off_sp, src_sp, meanp);
    gemm_tf32_kernel<<<gS, 128>>>(means, c1_ps_Wl, hs, c1_ps_Wr, c1_ps_bl, hs1, NSTK, HID, 2, 1);
    gemm_tf32_kernel<<<gP, 128>>>(meanp, c1_sp_Wl, hp, c1_sp_Wr, c1_sp_bl, hp1, NPOL, HID, 2, 1);

    // ---- conv2 (hs2 -> hs buffer, hp2 -> hp buffer; originals dead) ----
    agg_mean_kernel<<<NSTK, 128>>>(hp1, off_ps, src_ps, means);
    agg_mean_kernel<<<NPOL, 128>>>(hs1, off_sp, src_sp, meanp);
    gemm_tf32_kernel<<<gS, 128>>>(means, c2_ps_Wl, hs1, c2_ps_Wr, c2_ps_bl, hs, NSTK, HID, 2, 1);
    gemm_tf32_kernel<<<gP, 128>>>(meanp, c2_sp_Wl, hp1, c2_sp_Wr, c2_sp_bl, hp, NPOL, HID, 2, 1);

    // ---- decoder factorization: A = hp2 @ d1_W[0:512], B = hs2 @ d1_W[512:1024] ----
    gemm_tf32_kernel<<<gP, 128>>>(hp, d1_W, nullptr, nullptr, nullptr, Abuf, NPOL, HID, 1, 0);
    gemm_tf32_kernel<<<gS, 128>>>(hs, d1_W + (size_t)512 * HID, nullptr, nullptr, nullptr, Bbuf, NSTK, HID, 1, 0);

    // ---- fused per-edge decoder ----
    edge_decode_kernel<<<2048, 256>>>(Abuf, Bbuf, attr,
                                      d1_W + (size_t)1024 * HID,
                                      d1_W + (size_t)1025 * HID,
                                      d1_b, d2_W, d2_b, trow, tcol, out);
}

// round 2
// speedup vs baseline: 1.0079x; 1.0079x over previous
#include <cuda_runtime.h>
#include <mma.h>
#include <cstdint>

using namespace nvcuda;

#define NPOL 20000
#define NSTK 10000
#define EDG  400000
#define HID  512
#define NC   3

// padded row counts (multiples of BM=128) so GEMM epilogues need no bounds checks
#define PROWS 20096
#define SROWS 10112

// ---------------- device scratch (no allocations allowed) ----------------
__device__ float g_hp   [(size_t)PROWS * HID];
__device__ float g_hs   [(size_t)SROWS * HID];
__device__ float g_hp1  [(size_t)PROWS * HID];
__device__ float g_hs1  [(size_t)SROWS * HID];
__device__ float g_meanp[(size_t)PROWS * HID];
__device__ float g_means[(size_t)SROWS * HID];
__device__ float g_A    [(size_t)PROWS * HID];
__device__ float g_B    [(size_t)SROWS * HID];

__device__ int g_cnt_ps[NSTK];
__device__ int g_off_ps[NSTK + 1];
__device__ int g_cur_ps[NSTK];
__device__ int g_src_ps[EDG];

__device__ int g_cnt_sp[NPOL];
__device__ int g_off_sp[NPOL + 1];
__device__ int g_cur_sp[NPOL];
__device__ int g_src_sp[EDG];

// ---------------- CSR build ----------------
__global__ void zero2_kernel(int* a, int na, int* b, int nb) {
    int i  = blockIdx.x * blockDim.x + threadIdx.x;
    int st = gridDim.x * blockDim.x;
    for (int j = i; j < na; j += st) a[j] = 0;
    for (int j = i; j < nb; j += st) b[j] = 0;
}

__global__ void histo2_kernel(const int* __restrict__ d0, int* c0,
                              const int* __restrict__ d1, int* c1, int n) {
    int i  = blockIdx.x * blockDim.x + threadIdx.x;
    int st = gridDim.x * blockDim.x;
    for (int e = i; e < n; e += st) {
        atomicAdd(&c0[d0[e]], 1);
        atomicAdd(&c1[d1[e]], 1);
    }
}

__global__ __launch_bounds__(1024) void exscan2_kernel(
    const int* __restrict__ cnt0, int n0, int* off0, int* cur0,
    const int* __restrict__ cnt1, int n1, int* off1, int* cur1) {
    const int* cnt = blockIdx.x ? cnt1 : cnt0;
    int  n   = blockIdx.x ? n1 : n0;
    int* off = blockIdx.x ? off1 : off0;
    int* cur = blockIdx.x ? cur1 : cur0;

    __shared__ int buf[1024];
    __shared__ int s_carry;
    int tid = threadIdx.x;
    if (tid == 0) s_carry = 0;
    __syncthreads();

    for (int base = 0; base < n; base += 1024) {
        int i = base + tid;
        int v = (i < n) ? cnt[i] : 0;
        buf[tid] = v;
        __syncthreads();
        #pragma unroll
        for (int o = 1; o < 1024; o <<= 1) {
            int t = (tid >= o) ? buf[tid - o] : 0;
            __syncthreads();
            buf[tid] += t;
            __syncthreads();
        }
        int incl  = buf[tid];
        int total = buf[1023];
        if (i < n) {
            int ex = s_carry + incl - v;
            off[i] = ex;
            cur[i] = ex;
        }
        __syncthreads();
        if (tid == 0) s_carry += total;
        __syncthreads();
    }
    if (tid == 0) off[n] = s_carry;
}

__global__ void scatter2_kernel(const int* __restrict__ s0, const int* __restrict__ dd0,
                                int* cur0, int* o0,
                                const int* __restrict__ s1, const int* __restrict__ dd1,
                                int* cur1, int* o1, int n) {
    int i  = blockIdx.x * blockDim.x + threadIdx.x;
    int st = gridDim.x * blockDim.x;
    for (int e = i; e < n; e += st) {
        int p0 = atomicAdd(&cur0[dd0[e]], 1);
        o0[p0] = s0[e];
        int p1 = atomicAdd(&cur1[dd1[e]], 1);
        o1[p1] = s1[e];
    }
}

// ---------------- mean aggregation over CSR ----------------
__global__ __launch_bounds__(128) void agg_mean_kernel(
    const float* __restrict__ X, const int* __restrict__ off,
    const int* __restrict__ srcs, float* __restrict__ out) {
    int d   = blockIdx.x;
    int tid = threadIdx.x;
    int beg = off[d];
    int end = off[d + 1];

    __shared__ int sIdx[128];
    float4 acc = make_float4(0.f, 0.f, 0.f, 0.f);

    for (int cb = beg; cb < end; cb += 128) {
        int m = min(128, end - cb);
        if (tid < m) sIdx[tid] = srcs[cb + tid];
        __syncthreads();
        for (int j = 0; j < m; j++) {
            const float4* row = reinterpret_cast<const float4*>(X + (size_t)sIdx[j] * HID);
            float4 v = row[tid];
            acc.x += v.x; acc.y += v.y; acc.z += v.z; acc.w += v.w;
        }
        __syncthreads();
    }
    float inv = (end > beg) ? 1.0f / (float)(end - beg) : 0.0f;
    float4 r  = make_float4(acc.x * inv, acc.y * inv, acc.z * inv, acc.w * inv);
    reinterpret_cast<float4*>(out + (size_t)d * HID)[tid] = r;
}

// ---------------- cp.async helpers ----------------
__device__ __forceinline__ void cp_async16(void* dst, const void* src, bool pred) {
    uint32_t s = (uint32_t)__cvta_generic_to_shared(dst);
    int n = pred ? 16 : 0;
    asm volatile("cp.async.cg.shared.global [%0], [%1], 16, %2;\n" :: "r"(s), "l"(src), "r"(n));
}
__device__ __forceinline__ void cp_commit() {
    asm volatile("cp.async.commit_group;\n");
}
template <int N>
__device__ __forceinline__ void cp_wait() {
    asm volatile("cp.async.wait_group %0;\n" :: "n"(N));
}

// ---------------- tf32 WMMA GEMM ----------------
// C[M(pad),512] = act( sum_p Xp[M,K] @ Wp[K,512] + bias )
// BM=128, BN=128, BK=16, 256 threads (8 warps; warp tile 32x64 = 2x4 wmma frags)
// Double-buffered cp.async pipeline; bias folded via rank-1 mma chunk;
// epilogue stores straight to global (output buffers padded to BM).
#define BM 128
#define BN 128
#define BK 16
#define XLD 24
#define WLD 136

__global__ __launch_bounds__(256) void gemm_tf32_kernel(
    const float* __restrict__ X0, const float* __restrict__ W0,
    const float* __restrict__ X1, const float* __restrict__ W1,
    const float* __restrict__ bias, float* __restrict__ C,
    int M, int K, int npair, int dorelu) {
    __shared__ float Xs[2][BM][XLD];
    __shared__ float Ws[2][BK][WLD];

    const int row0 = blockIdx.x * BM;
    const int n0   = blockIdx.y * BN;
    const int tid  = threadIdx.x;
    const int warp = tid >> 5;
    const int wm   = warp >> 1;   // 0..3
    const int wn   = warp & 1;    // 0..1

    wmma::fragment<wmma::accumulator, 16, 16, 8, float> acc[2][4];
    #pragma unroll
    for (int i = 0; i < 2; i++)
        #pragma unroll
        for (int j = 0; j < 4; j++)
            wmma::fill_fragment(acc[i][j], 0.0f);

    const int TK = K / BK;
    const int T  = npair * TK;

    // loader index precompute
    const int xr = tid >> 2;           // 0..63
    const int xc = (tid & 3) * 4;      // 0,4,8,12
    const int wr = tid >> 5;           // 0..7
    const int wc = (tid & 31) * 4;     // 0..124

    auto load_tile = [&](int t, int buf) {
        const float* X = (t >= TK) ? X1 : X0;
        const float* W = (t >= TK) ? W1 : W0;
        const int k0 = ((t >= TK) ? (t - TK) : t) * BK;
        int rg0 = row0 + xr;
        int rg1 = row0 + xr + 64;
        cp_async16(&Xs[buf][xr][xc],      X + (size_t)rg0 * K + k0 + xc, rg0 < M);
        cp_async16(&Xs[buf][xr + 64][xc], X + (size_t)rg1 * K + k0 + xc, rg1 < M);
        cp_async16(&Ws[buf][wr][wc],      W + (size_t)(k0 + wr) * HID + n0 + wc, true);
        cp_async16(&Ws[buf][wr + 8][wc],  W + (size_t)(k0 + wr + 8) * HID + n0 + wc, true);
    };

    auto compute = [&](int buf) {
        #pragma unroll
        for (int kk = 0; kk < BK; kk += 8) {
            wmma::fragment<wmma::matrix_a, 16, 16, 8, wmma::precision::tf32, wmma::row_major> a[2];
            wmma::fragment<wmma::matrix_b, 16, 16, 8, wmma::precision::tf32, wmma::row_major> b[4];
            #pragma unroll
            for (int i = 0; i < 2; i++) {
                wmma::load_matrix_sync(a[i], &Xs[buf][wm * 32 + i * 16][kk], XLD);
                #pragma unroll
                for (int t = 0; t < a[i].num_elements; t++)
                    a[i].x[t] = wmma::__float_to_tf32(a[i].x[t]);
            }
            #pragma unroll
            for (int j = 0; j < 4; j++) {
                wmma::load_matrix_sync(b[j], &Ws[buf][kk][wn * 64 + j * 16], WLD);
                #pragma unroll
                for (int t = 0; t < b[j].num_elements; t++)
                    b[j].x[t] = wmma::__float_to_tf32(b[j].x[t]);
            }
            #pragma unroll
            for (int i = 0; i < 2; i++)
                #pragma unroll
                for (int j = 0; j < 4; j++)
                    wmma::mma_sync(acc[i][j], a[i], b[j], acc[i][j]);
        }
    };

    load_tile(0, 0);
    cp_commit();
    int buf = 0;
    for (int t = 0; t < T; t++) {
        if (t + 1 < T) { load_tile(t + 1, buf ^ 1); cp_commit(); }
        if (t + 1 < T) cp_wait<1>(); else cp_wait<0>();
        __syncthreads();
        compute(buf);
        __syncthreads();
        buf ^= 1;
    }

    if (bias) {
        // rank-1 bias chunk: Xs col0 = 1 (rest 0), Ws row0 = bias (rest 0)
        for (int idx = tid; idx < BM * BK; idx += 256)
            Xs[0][idx >> 4][idx & 15] = ((idx & 15) == 0) ? 1.0f : 0.0f;
        for (int idx = tid; idx < BK * BN; idx += 256) {
            int r = idx >> 7, c = idx & 127;
            Ws[0][r][c] = (r == 0) ? bias[n0 + c] : 0.0f;
        }
        __syncthreads();
        compute(0);
        __syncthreads();
    }

    #pragma unroll
    for (int i = 0; i < 2; i++) {
        #pragma unroll
        for (int j = 0; j < 4; j++) {
            if (dorelu) {
                #pragma unroll
                for (int t = 0; t < acc[i][j].num_elements; t++)
                    acc[i][j].x[t] = fmaxf(acc[i][j].x[t], 0.0f);
            }
            wmma::store_matrix_sync(
                C + (size_t)(row0 + wm * 32 + i * 16) * HID + n0 + wn * 64 + j * 16,
                acc[i][j], HID, wmma::mem_row_major);
        }
    }
}

// ---------------- fused per-edge decoder ----------------
__global__ __launch_bounds__(256) void edge_decode_kernel(
    const float* __restrict__ Aa, const float* __restrict__ Bb,
    const float* __restrict__ attr,
    const float* __restrict__ w0, const float* __restrict__ w1,
    const float* __restrict__ b1,
    const float* __restrict__ d2W, const float* __restrict__ d2b,
    const int* __restrict__ erow, const int* __restrict__ ecol,
    float* __restrict__ out) {
    __shared__ float4 s_w0[128], s_w1[128], s_b[128], s_d0[128], s_d1[128], s_d2[128];
    int tid = threadIdx.x;
    for (int i = tid; i < HID; i += 256) {
        ((float*)s_w0)[i] = w0[i];
        ((float*)s_w1)[i] = w1[i];
        ((float*)s_b)[i]  = b1[i];
        ((float*)s_d0)[i] = d2W[i * 3 + 0];
        ((float*)s_d1)[i] = d2W[i * 3 + 1];
        ((float*)s_d2)[i] = d2W[i * 3 + 2];
    }
    __syncthreads();
    float db0 = d2b[0], db1 = d2b[1], db2 = d2b[2];
    int lane = tid & 31;
    int warp = tid >> 5;

    for (int e = blockIdx.x * 8 + warp; e < EDG; e += gridDim.x * 8) {
        int r = erow[e];
        int c = ecol[e];
        float a0 = attr[2 * e];
        float a1 = attr[2 * e + 1];
        const float4* A4 = reinterpret_cast<const float4*>(Aa + (size_t)r * HID);
        const float4* B4 = reinterpret_cast<const float4*>(Bb + (size_t)c * HID);
        float s0 = 0.f, s1 = 0.f, s2 = 0.f;
        #pragma unroll
        for (int k = 0; k < 4; k++) {
            int q = k * 32 + lane;
            float4 va = A4[q], vb = B4[q];
            float4 vw0 = s_w0[q], vw1 = s_w1[q], vbb = s_b[q];
            float4 v0 = s_d0[q], v1 = s_d1[q], v2 = s_d2[q];
            float h;
            h = fmaxf(va.x + vb.x + a0 * vw0.x + a1 * vw1.x + vbb.x, 0.f);
            s0 += h * v0.x; s1 += h * v1.x; s2 += h * v2.x;
            h = fmaxf(va.y + vb.y + a0 * vw0.y + a1 * vw1.y + vbb.y, 0.f);
            s0 += h * v0.y; s1 += h * v1.y; s2 += h * v2.y;
            h = fmaxf(va.z + vb.z + a0 * vw0.z + a1 * vw1.z + vbb.z, 0.f);
            s0 += h * v0.z; s1 += h * v1.z; s2 += h * v2.z;
            h = fmaxf(va.w + vb.w + a0 * vw0.w + a1 * vw1.w + vbb.w, 0.f);
            s0 += h * v0.w; s1 += h * v1.w; s2 += h * v2.w;
        }
        #pragma unroll
        for (int o = 16; o > 0; o >>= 1) {
            s0 += __shfl_xor_sync(0xffffffffu, s0, o);
            s1 += __shfl_xor_sync(0xffffffffu, s1, o);
            s2 += __shfl_xor_sync(0xffffffffu, s2, o);
        }
        if (lane == 0) {
            out[(size_t)e * 3 + 0] = s0 + db0;
            out[(size_t)e * 3 + 1] = s1 + db1;
            out[(size_t)e * 3 + 2] = s2 + db2;
        }
    }
}

// ---------------- host launch ----------------
extern "C" void kernel_launch(void* const* d_in, const int* in_sizes, int n_in,
                              void* d_out, int out_size) {
    (void)in_sizes; (void)n_in; (void)out_size;

    const float* x_pol = (const float*)d_in[0];
    const float* x_stk = (const float*)d_in[1];
    const float* attr  = (const float*)d_in[2];
    const float* Wp    = (const float*)d_in[3];
    const float* bp    = (const float*)d_in[4];
    const float* Ws    = (const float*)d_in[5];
    const float* bs    = (const float*)d_in[6];
    const float* c1_ps_Wl = (const float*)d_in[7];
    const float* c1_ps_bl = (const float*)d_in[8];
    const float* c1_ps_Wr = (const float*)d_in[9];
    const float* c1_sp_Wl = (const float*)d_in[10];
    const float* c1_sp_bl = (const float*)d_in[11];
    const float* c1_sp_Wr = (const float*)d_in[12];
    const float* c2_ps_Wl = (const float*)d_in[13];
    const float* c2_ps_bl = (const float*)d_in[14];
    const float* c2_ps_Wr = (const float*)d_in[15];
    const float* c2_sp_Wl = (const float*)d_in[16];
    const float* c2_sp_bl = (const float*)d_in[17];
    const float* c2_sp_Wr = (const float*)d_in[18];
    const float* d1_W  = (const float*)d_in[19];   // [1026, 512] row-major
    const float* d1_b  = (const float*)d_in[20];
    const float* d2_W  = (const float*)d_in[21];   // [512, 3]
    const float* d2_b  = (const float*)d_in[22];
    const int* eps_src = (const int*)d_in[23];
    const int* eps_dst = (const int*)d_in[24];
    const int* esp_src = (const int*)d_in[25];
    const int* esp_dst = (const int*)d_in[26];
    const int* trow    = (const int*)d_in[27];
    const int* tcol    = (const int*)d_in[28];
    float* out = (float*)d_out;

    void* p;
    cudaGetSymbolAddress(&p, g_hp);     float* hp    = (float*)p;
    cudaGetSymbolAddress(&p, g_hs);     float* hs    = (float*)p;
    cudaGetSymbolAddress(&p, g_hp1);    float* hp1   = (float*)p;
    cudaGetSymbolAddress(&p, g_hs1);    float* hs1   = (float*)p;
    cudaGetSymbolAddress(&p, g_meanp);  float* meanp = (float*)p;
    cudaGetSymbolAddress(&p, g_means);  float* means = (float*)p;
    cudaGetSymbolAddress(&p, g_A);      float* Abuf  = (float*)p;
    cudaGetSymbolAddress(&p, g_B);      float* Bbuf  = (float*)p;
    cudaGetSymbolAddress(&p, g_cnt_ps); int* cnt_ps = (int*)p;
    cudaGetSymbolAddress(&p, g_off_ps); int* off_ps = (int*)p;
    cudaGetSymbolAddress(&p, g_cur_ps); int* cur_ps = (int*)p;
    cudaGetSymbolAddress(&p, g_src_ps); int* src_ps = (int*)p;
    cudaGetSymbolAddress(&p, g_cnt_sp); int* cnt_sp = (int*)p;
    cudaGetSymbolAddress(&p, g_off_sp); int* off_sp = (int*)p;
    cudaGetSymbolAddress(&p, g_cur_sp); int* cur_sp = (int*)p;
    cudaGetSymbolAddress(&p, g_src_sp); int* src_sp = (int*)p;

    // ---- CSR build (both relations) ----
    zero2_kernel<<<64, 256>>>(cnt_ps, NSTK, cnt_sp, NPOL);
    histo2_kernel<<<400, 256>>>(eps_dst, cnt_ps, esp_dst, cnt_sp, EDG);
    exscan2_kernel<<<2, 1024>>>(cnt_ps, NSTK, off_ps, cur_ps,
                                cnt_sp, NPOL, off_sp, cur_sp);
    scatter2_kernel<<<400, 256>>>(eps_src, eps_dst, cur_ps, src_ps,
                                  esp_src, esp_dst, cur_sp, src_sp, EDG);

    dim3 gP(PROWS / BM, HID / BN);   // (157, 4)
    dim3 gS(SROWS / BM, HID / BN);   // (79, 4)

    // ---- input projections ----
    gemm_tf32_kernel<<<gP, 256>>>(x_pol, Wp, nullptr, nullptr, bp, hp, NPOL, 64, 1, 1);
    gemm_tf32_kernel<<<gS, 256>>>(x_stk, Ws, nullptr, nullptr, bs, hs, NSTK, 64, 1, 1);

    // ---- conv1 ----
    agg_mean_kernel<<<NSTK, 128>>>(hp, off_ps, src_ps, means);
    agg_mean_kernel<<<NPOL, 128>>>(hs, off_sp, src_sp, meanp);
    gemm_tf32_kernel<<<gS, 256>>>(means, c1_ps_Wl, hs, c1_ps_Wr, c1_ps_bl, hs1, NSTK, HID, 2, 1);
    gemm_tf32_kernel<<<gP, 256>>>(meanp, c1_sp_Wl, hp, c1_sp_Wr, c1_sp_bl, hp1, NPOL, HID, 2, 1);

    // ---- conv2 (hs2 -> hs buffer, hp2 -> hp buffer; originals dead) ----
    agg_mean_kernel<<<NSTK, 128>>>(hp1, off_ps, src_ps, means);
    agg_mean_kernel<<<NPOL, 128>>>(hs1, off_sp, src_sp, meanp);
    gemm_tf32_kernel<<<gS, 256>>>(means, c2_ps_Wl, hs1, c2_ps_Wr, c2_ps_bl, hs, NSTK, HID, 2, 1);
    gemm_tf32_kernel<<<gP, 256>>>(meanp, c2_sp_Wl, hp1, c2_sp_Wr, c2_sp_bl, hp, NPOL, HID, 2, 1);

    // ---- decoder factorization: A = hp2 @ d1_W[0:512], B = hs2 @ d1_W[512:1024] ----
    gemm_tf32_kernel<<<gP, 256>>>(hp, d1_W, nullptr, nullptr, nullptr, Abuf, NPOL, HID, 1, 0);
    gemm_tf32_kernel<<<gS, 256>>>(hs, d1_W + (size_t)512 * HID, nullptr, nullptr, nullptr, Bbuf, NSTK, HID, 1, 0);

    // ---- fused per-edge decoder ----
    edge_decode_kernel<<<2048, 256>>>(Abuf, Bbuf, attr,
                                      d1_W + (size_t)1024 * HID,
                                      d1_W + (size_t)1025 * HID,
                                      d1_b, d2_W, d2_b, trow, tcol, out);
}

// round 4
// speedup vs baseline: 2.1110x; 2.0946x over previous
#include <cuda_runtime.h>
#include <cuda_fp16.h>
#include <mma.h>
#include <cstdint>

using namespace nvcuda;

#define NPOL 20000
#define NSTK 10000
#define EDG  400000
#define HID  512
#define NC   3

// padded row counts (multiples of 128) so GEMM epilogues need no bounds checks
#define PROWS 20096
#define SROWS 10112

#define WBIG (512 * 512)
#define WSML (64 * 512)

// ---------------- device scratch ----------------
__device__ float g_hp [(size_t)PROWS * HID];
__device__ float g_hs [(size_t)SROWS * HID];
__device__ float g_hp1[(size_t)PROWS * HID];
__device__ float g_hs1[(size_t)SROWS * HID];
__device__ float g_A  [(size_t)PROWS * HID];
__device__ float g_B  [(size_t)SROWS * HID];

__device__ __half g_hp16  [(size_t)PROWS * HID];
__device__ __half g_hs16  [(size_t)SROWS * HID];
__device__ __half g_hp116 [(size_t)PROWS * HID];
__device__ __half g_hs116 [(size_t)SROWS * HID];
__device__ __half g_hp216 [(size_t)PROWS * HID];
__device__ __half g_hs216 [(size_t)SROWS * HID];
__device__ __half g_meanp16[(size_t)PROWS * HID];
__device__ __half g_means16[(size_t)SROWS * HID];

__device__ __half g_w16[10 * WBIG + 2 * WSML];
__device__ __half g_xp16[(size_t)NPOL * 64];
__device__ __half g_xs16[(size_t)NSTK * 64];

__device__ int g_cnt_ps[NSTK];
__device__ int g_off_ps[NSTK + 1];
__device__ int g_cur_ps[NSTK];
__device__ int g_src_ps[EDG];

__device__ int g_cnt_sp[NPOL];
__device__ int g_off_sp[NPOL + 1];
__device__ int g_cur_sp[NPOL];
__device__ int g_src_sp[EDG];

// ---------------- f32 -> f16 converts ----------------
struct CPack {
    const float* src[14];
    __half*      dst[14];
    int          cnt[14];   // element counts, all multiples of 4
};

__global__ __launch_bounds__(256) void convert_all_kernel(CPack p) {
    int s = blockIdx.y;
    const float4* src = reinterpret_cast<const float4*>(p.src[s]);
    __half2* dst = reinterpret_cast<__half2*>(p.dst[s]);
    int n4 = p.cnt[s] >> 2;
    for (int i = blockIdx.x * blockDim.x + threadIdx.x; i < n4; i += gridDim.x * blockDim.x) {
        float4 v = src[i];
        dst[2 * i]     = __floats2half2_rn(v.x, v.y);
        dst[2 * i + 1] = __floats2half2_rn(v.z, v.w);
    }
}

__global__ __launch_bounds__(256) void convert2_kernel(
    const float* s0, __half* d0, int n0,
    const float* s1, __half* d1, int n1) {
    const float4* src = reinterpret_cast<const float4*>(blockIdx.y ? s1 : s0);
    __half2* dst = reinterpret_cast<__half2*>(blockIdx.y ? d1 : d0);
    int n4 = (blockIdx.y ? n1 : n0) >> 2;
    for (int i = blockIdx.x * blockDim.x + threadIdx.x; i < n4; i += gridDim.x * blockDim.x) {
        float4 v = src[i];
        dst[2 * i]     = __floats2half2_rn(v.x, v.y);
        dst[2 * i + 1] = __floats2half2_rn(v.z, v.w);
    }
}

// ---------------- CSR build ----------------
__global__ void zero2_kernel(int* a, int na, int* b, int nb) {
    int i  = blockIdx.x * blockDim.x + threadIdx.x;
    int st = gridDim.x * blockDim.x;
    for (int j = i; j < na; j += st) a[j] = 0;
    for (int j = i; j < nb; j += st) b[j] = 0;
}

__global__ void histo2_kernel(const int* __restrict__ d0, int* c0,
                              const int* __restrict__ d1, int* c1, int n) {
    int i  = blockIdx.x * blockDim.x + threadIdx.x;
    int st = gridDim.x * blockDim.x;
    for (int e = i; e < n; e += st) {
        atomicAdd(&c0[d0[e]], 1);
        atomicAdd(&c1[d1[e]], 1);
    }
}

__global__ __launch_bounds__(1024) void exscan2_kernel(
    const int* __restrict__ cnt0, int n0, int* off0, int* cur0,
    const int* __restrict__ cnt1, int n1, int* off1, int* cur1) {
    const int* cnt = blockIdx.x ? cnt1 : cnt0;
    int  n   = blockIdx.x ? n1 : n0;
    int* off = blockIdx.x ? off1 : off0;
    int* cur = blockIdx.x ? cur1 : cur0;

    __shared__ int buf[1024];
    __shared__ int s_carry;
    int tid = threadIdx.x;
    if (tid == 0) s_carry = 0;
    __syncthreads();

    for (int base = 0; base < n; base += 1024) {
        int i = base + tid;
        int v = (i < n) ? cnt[i] : 0;
        buf[tid] = v;
        __syncthreads();
        #pragma unroll
        for (int o = 1; o < 1024; o <<= 1) {
            int t = (tid >= o) ? buf[tid - o] : 0;
            __syncthreads();
            buf[tid] += t;
            __syncthreads();
        }
        int incl  = buf[tid];
        int total = buf[1023];
        if (i < n) {
            int ex = s_carry + incl - v;
            off[i] = ex;
            cur[i] = ex;
        }
        __syncthreads();
        if (tid == 0) s_carry += total;
        __syncthreads();
    }
    if (tid == 0) off[n] = s_carry;
}

__global__ void scatter2_kernel(const int* __restrict__ s0, const int* __restrict__ dd0,
                                int* cur0, int* o0,
                                const int* __restrict__ s1, const int* __restrict__ dd1,
                                int* cur1, int* o1, int n) {
    int i  = blockIdx.x * blockDim.x + threadIdx.x;
    int st = gridDim.x * blockDim.x;
    for (int e = i; e < n; e += st) {
        int p0 = atomicAdd(&cur0[dd0[e]], 1);
        o0[p0] = s0[e];
        int p1 = atomicAdd(&cur1[dd1[e]], 1);
        o1[p1] = s1[e];
    }
}

// ---------------- mean aggregation over CSR (f32 in, f16 out) ----------------
__global__ __launch_bounds__(128) void agg_mean_kernel(
    const float* __restrict__ X, const int* __restrict__ off,
    const int* __restrict__ srcs, __half* __restrict__ out) {
    int d   = blockIdx.x;
    int tid = threadIdx.x;
    int beg = off[d];
    int end = off[d + 1];

    __shared__ int sIdx[128];
    float4 acc = make_float4(0.f, 0.f, 0.f, 0.f);

    for (int cb = beg; cb < end; cb += 128) {
        int m = min(128, end - cb);
        if (tid < m) sIdx[tid] = srcs[cb + tid];
        __syncthreads();
        for (int j = 0; j < m; j++) {
            const float4* row = reinterpret_cast<const float4*>(X + (size_t)sIdx[j] * HID);
            float4 v = row[tid];
            acc.x += v.x; acc.y += v.y; acc.z += v.z; acc.w += v.w;
        }
        __syncthreads();
    }
    float inv = (end > beg) ? 1.0f / (float)(end - beg) : 0.0f;
    __half2* o = reinterpret_cast<__half2*>(out + (size_t)d * HID) + tid * 2;
    o[0] = __floats2half2_rn(acc.x * inv, acc.y * inv);
    o[1] = __floats2half2_rn(acc.z * inv, acc.w * inv);
}

// ---------------- cp.async helpers ----------------
__device__ __forceinline__ void cp_async16(void* dst, const void* src, bool pred) {
    uint32_t s = (uint32_t)__cvta_generic_to_shared(dst);
    int n = pred ? 16 : 0;
    asm volatile("cp.async.cg.shared.global [%0], [%1], 16, %2;\n" :: "r"(s), "l"(src), "r"(n));
}
__device__ __forceinline__ void cp_commit() { asm volatile("cp.async.commit_group;\n"); }
template <int N>
__device__ __forceinline__ void cp_wait() { asm volatile("cp.async.wait_group %0;\n" :: "n"(N)); }

// ---------------- fp16 WMMA GEMM ----------------
// C[M(pad),512] = act( sum_p Xp[M,K] @ Wp[K,512] + bias ),  all operands fp16, accum fp32
// BM=128, BN=128, BK=32 halves, 256 threads (8 warps; warp tile 32x64 = 2x4 m16n16k16 frags)
// Double-buffered cp.async; bias folded as rank-1 fp16 chunk; outputs f32.
#define XLDH 40
#define WLDH 136

__global__ __launch_bounds__(256) void gemm_fp16_kernel(
    const __half* __restrict__ X0, const __half* __restrict__ W0,
    const __half* __restrict__ X1, const __half* __restrict__ W1,
    const float* __restrict__ bias, float* __restrict__ C,
    int M, int K, int npair, int dorelu) {
    __shared__ __half Xs[2][128][XLDH];
    __shared__ __half Ws[2][32][WLDH];

    const int row0 = blockIdx.x * 128;
    const int n0   = blockIdx.y * 128;
    const int tid  = threadIdx.x;
    const int warp = tid >> 5;
    const int wm   = warp >> 1;   // 0..3
    const int wn   = warp & 1;    // 0..1

    wmma::fragment<wmma::accumulator, 16, 16, 16, float> acc[2][4];
    #pragma unroll
    for (int i = 0; i < 2; i++)
        #pragma unroll
        for (int j = 0; j < 4; j++)
            wmma::fill_fragment(acc[i][j], 0.0f);

    const int CK = K >> 5;
    const int T  = npair * CK;

    auto load_chunk = [&](int c, int buf) {
        int pair = (c >= CK) ? 1 : 0;
        const __half* X = pair ? X1 : X0;
        const __half* W = pair ? W1 : W0;
        int kk = (c - pair * CK) * 32;
        // A tile: 128 rows x 32 halves (64B/row) = 512 16B units
        #pragma unroll
        for (int q = 0; q < 2; q++) {
            int u = tid + q * 256;
            int r = u >> 2, cu = u & 3;
            int rg = row0 + r;
            cp_async16(&Xs[buf][r][cu * 8], X + (size_t)rg * K + kk + cu * 8, rg < M);
        }
        // B tile: 32 rows x 128 halves (256B/row) = 512 units
        #pragma unroll
        for (int q = 0; q < 2; q++) {
            int u = tid + q * 256;
            int r = u >> 4, cu = u & 15;
            cp_async16(&Ws[buf][r][cu * 8], W + (size_t)(kk + r) * HID + n0 + cu * 8, true);
        }
        cp_commit();
    };

    auto compute = [&](int buf, int nk) {
        for (int kk = 0; kk < nk; kk += 16) {
            wmma::fragment<wmma::matrix_a, 16, 16, 16, __half, wmma::row_major> a[2];
            wmma::fragment<wmma::matrix_b, 16, 16, 16, __half, wmma::row_major> b[4];
            #pragma unroll
            for (int i = 0; i < 2; i++)
                wmma::load_matrix_sync(a[i], &Xs[buf][wm * 32 + i * 16][kk], XLDH);
            #pragma unroll
            for (int j = 0; j < 4; j++)
                wmma::load_matrix_sync(b[j], &Ws[buf][kk][wn * 64 + j * 16], WLDH);
            #pragma unroll
            for (int i = 0; i < 2; i++)
                #pragma unroll
                for (int j = 0; j < 4; j++)
                    wmma::mma_sync(acc[i][j], a[i], b[j], acc[i][j]);
        }
    };

    load_chunk(0, 0);
    int buf = 0;
    for (int t = 0; t < T; t++) {
        if (t + 1 < T) load_chunk(t + 1, buf ^ 1);
        if (t + 1 < T) cp_wait<1>(); else cp_wait<0>();
        __syncthreads();
        compute(buf, 32);
        __syncthreads();
        buf ^= 1;
    }

    if (bias) {
        // rank-1 bias chunk: Xs col0 = 1 (rest 0); Ws row0 = bias (rest 0). K=16.
        for (int u = tid; u < 128 * 16; u += 256) {
            int r = u >> 4, c = u & 15;
            Xs[0][r][c] = __float2half((c == 0) ? 1.0f : 0.0f);
        }
        for (int u = tid; u < 16 * 128; u += 256) {
            int r = u >> 7, c = u & 127;
            Ws[0][r][c] = __float2half((r == 0) ? bias[n0 + c] : 0.0f);
        }
        __syncthreads();
        compute(0, 16);
        __syncthreads();
    }

    #pragma unroll
    for (int i = 0; i < 2; i++) {
        #pragma unroll
        for (int j = 0; j < 4; j++) {
            if (dorelu) {
                #pragma unroll
                for (int t = 0; t < acc[i][j].num_elements; t++)
                    acc[i][j].x[t] = fmaxf(acc[i][j].x[t], 0.0f);
            }
            wmma::store_matrix_sync(
                C + (size_t)(row0 + wm * 32 + i * 16) * HID + n0 + wn * 64 + j * 16,
                acc[i][j], HID, wmma::mem_row_major);
        }
    }
}

// ---------------- fused per-edge decoder ----------------
__global__ __launch_bounds__(256) void edge_decode_kernel(
    const float* __restrict__ Aa, const float* __restrict__ Bb,
    const float* __restrict__ attr,
    const float* __restrict__ w0, const float* __restrict__ w1,
    const float* __restrict__ b1,
    const float* __restrict__ d2W, const float* __restrict__ d2b,
    const int* __restrict__ erow, const int* __restrict__ ecol,
    float* __restrict__ out) {
    __shared__ float4 s_w0[128], s_w1[128], s_b[128], s_d0[128], s_d1[128], s_d2[128];
    int tid = threadIdx.x;
    for (int i = tid; i < HID; i += 256) {
        ((float*)s_w0)[i] = w0[i];
        ((float*)s_w1)[i] = w1[i];
        ((float*)s_b)[i]  = b1[i];
        ((float*)s_d0)[i] = d2W[i * 3 + 0];
        ((float*)s_d1)[i] = d2W[i * 3 + 1];
        ((float*)s_d2)[i] = d2W[i * 3 + 2];
    }
    __syncthreads();
    float db0 = d2b[0], db1 = d2b[1], db2 = d2b[2];
    int lane = tid & 31;
    int warp = tid >> 5;

    for (int e = blockIdx.x * 8 + warp; e < EDG; e += gridDim.x * 8) {
        int r = erow[e];
        int c = ecol[e];
        float a0 = attr[2 * e];
        float a1 = attr[2 * e + 1];
        const float4* A4 = reinterpret_cast<const float4*>(Aa + (size_t)r * HID);
        const float4* B4 = reinterpret_cast<const float4*>(Bb + (size_t)c * HID);
        float s0 = 0.f, s1 = 0.f, s2 = 0.f;
        #pragma unroll
        for (int k = 0; k < 4; k++) {
            int q = k * 32 + lane;
            float4 va = A4[q], vb = B4[q];
            float4 vw0 = s_w0[q], vw1 = s_w1[q], vbb = s_b[q];
            float4 v0 = s_d0[q], v1 = s_d1[q], v2 = s_d2[q];
            float h;
            h = fmaxf(va.x + vb.x + a0 * vw0.x + a1 * vw1.x + vbb.x, 0.f);
            s0 += h * v0.x; s1 += h * v1.x; s2 += h * v2.x;
            h = fmaxf(va.y + vb.y + a0 * vw0.y + a1 * vw1.y + vbb.y, 0.f);
            s0 += h * v0.y; s1 += h * v1.y; s2 += h * v2.y;
            h = fmaxf(va.z + vb.z + a0 * vw0.z + a1 * vw1.z + vbb.z, 0.f);
            s0 += h * v0.z; s1 += h * v1.z; s2 += h * v2.z;
            h = fmaxf(va.w + vb.w + a0 * vw0.w + a1 * vw1.w + vbb.w, 0.f);
            s0 += h * v0.w; s1 += h * v1.w; s2 += h * v2.w;
        }
        #pragma unroll
        for (int o = 16; o > 0; o >>= 1) {
            s0 += __shfl_xor_sync(0xffffffffu, s0, o);
            s1 += __shfl_xor_sync(0xffffffffu, s1, o);
            s2 += __shfl_xor_sync(0xffffffffu, s2, o);
        }
        if (lane == 0) {
            out[(size_t)e * 3 + 0] = s0 + db0;
            out[(size_t)e * 3 + 1] = s1 + db1;
            out[(size_t)e * 3 + 2] = s2 + db2;
        }
    }
}

// ---------------- host launch ----------------
extern "C" void kernel_launch(void* const* d_in, const int* in_sizes, int n_in,
                              void* d_out, int out_size) {
    (void)in_sizes; (void)n_in; (void)out_size;

    const float* x_pol = (const float*)d_in[0];
    const float* x_stk = (const float*)d_in[1];
    const float* attr  = (const float*)d_in[2];
    const float* Wp    = (const float*)d_in[3];
    const float* bp    = (const float*)d_in[4];
    const float* Ws    = (const float*)d_in[5];
    const float* bs    = (const float*)d_in[6];
    const float* c1_ps_Wl = (const float*)d_in[7];
    const float* c1_ps_bl = (const float*)d_in[8];
    const float* c1_ps_Wr = (const float*)d_in[9];
    const float* c1_sp_Wl = (const float*)d_in[10];
    const float* c1_sp_bl = (const float*)d_in[11];
    const float* c1_sp_Wr = (const float*)d_in[12];
    const float* c2_ps_Wl = (const float*)d_in[13];
    const float* c2_ps_bl = (const float*)d_in[14];
    const float* c2_ps_Wr = (const float*)d_in[15];
    const float* c2_sp_Wl = (const float*)d_in[16];
    const float* c2_sp_bl = (const float*)d_in[17];
    const float* c2_sp_Wr = (const float*)d_in[18];
    const float* d1_W  = (const float*)d_in[19];   // [1026, 512]
    const float* d1_b  = (const float*)d_in[20];
    const float* d2_W  = (const float*)d_in[21];   // [512, 3]
    const float* d2_b  = (const float*)d_in[22];
    const int* eps_src = (const int*)d_in[23];
    const int* eps_dst = (const int*)d_in[24];
    const int* esp_src = (const int*)d_in[25];
    const int* esp_dst = (const int*)d_in[26];
    const int* trow    = (const int*)d_in[27];
    const int* tcol    = (const int*)d_in[28];
    float* out = (float*)d_out;

    void* p;
    cudaGetSymbolAddress(&p, g_hp);      float* hp    = (float*)p;
    cudaGetSymbolAddress(&p, g_hs);      float* hs    = (float*)p;
    cudaGetSymbolAddress(&p, g_hp1);     float* hp1   = (float*)p;
    cudaGetSymbolAddress(&p, g_hs1);     float* hs1   = (float*)p;
    cudaGetSymbolAddress(&p, g_A);       float* Abuf  = (float*)p;
    cudaGetSymbolAddress(&p, g_B);       float* Bbuf  = (float*)p;
    cudaGetSymbolAddress(&p, g_hp16);    __half* hp16   = (__half*)p;
    cudaGetSymbolAddress(&p, g_hs16);    __half* hs16   = (__half*)p;
    cudaGetSymbolAddress(&p, g_hp116);   __half* hp116  = (__half*)p;
    cudaGetSymbolAddress(&p, g_hs116);   __half* hs116  = (__half*)p;
    cudaGetSymbolAddress(&p, g_hp216);   __half* hp216  = (__half*)p;
    cudaGetSymbolAddress(&p, g_hs216);   __half* hs216  = (__half*)p;
    cudaGetSymbolAddress(&p, g_meanp16); __half* meanp16 = (__half*)p;
    cudaGetSymbolAddress(&p, g_means16); __half* means16 = (__half*)p;
    cudaGetSymbolAddress(&p, g_w16);     __half* w16    = (__half*)p;
    cudaGetSymbolAddress(&p, g_xp16);    __half* xp16   = (__half*)p;
    cudaGetSymbolAddress(&p, g_xs16);    __half* xs16   = (__half*)p;
    cudaGetSymbolAddress(&p, g_cnt_ps);  int* cnt_ps = (int*)p;
    cudaGetSymbolAddress(&p, g_off_ps);  int* off_ps = (int*)p;
    cudaGetSymbolAddress(&p, g_cur_ps);  int* cur_ps = (int*)p;
    cudaGetSymbolAddress(&p, g_src_ps);  int* src_ps = (int*)p;
    cudaGetSymbolAddress(&p, g_cnt_sp);  int* cnt_sp = (int*)p;
    cudaGetSymbolAddress(&p, g_off_sp);  int* off_sp = (int*)p;
    cudaGetSymbolAddress(&p, g_cur_sp);  int* cur_sp = (int*)p;
    cudaGetSymbolAddress(&p, g_src_sp);  int* src_sp = (int*)p;

    // fp16 weight table: 10 big [512,512] + 2 small [64,512], layout preserved
    __half* w[12];
    const float* wsrc[12] = {c1_ps_Wl, c1_ps_Wr, c1_sp_Wl, c1_sp_Wr,
                             c2_ps_Wl, c2_ps_Wr, c2_sp_Wl, c2_sp_Wr,
                             d1_W, d1_W + (size_t)512 * HID, Wp, Ws};
    for (int i = 0; i < 10; i++) w[i] = w16 + (size_t)i * WBIG;
    w[10] = w16 + (size_t)10 * WBIG;
    w[11] = w16 + (size_t)10 * WBIG + WSML;

    CPack cp;
    for (int i = 0; i < 12; i++) { cp.src[i] = wsrc[i]; cp.dst[i] = w[i]; cp.cnt[i] = (i < 10) ? WBIG : WSML; }
    cp.src[12] = x_pol; cp.dst[12] = xp16; cp.cnt[12] = NPOL * 64;
    cp.src[13] = x_stk; cp.dst[13] = xs16; cp.cnt[13] = NSTK * 64;

    dim3 gP(PROWS / 128, 4);
    dim3 gS(SROWS / 128, 4);
    dim3 cgrid(256, 14);
    dim3 c2grid(512, 2);

    // 1: converts
    convert_all_kernel<<<cgrid, 256>>>(cp);
    // 2-3: CSR histogram
    zero2_kernel<<<64, 256>>>(cnt_ps, NSTK, cnt_sp, NPOL);
    histo2_kernel<<<400, 256>>>(eps_dst, cnt_ps, esp_dst, cnt_sp, EDG);
    // 4-5: input projections (fp16 wmma) — slot 4 is the ncu capture target
    gemm_fp16_kernel<<<gP, 256>>>(xp16, w[10], nullptr, nullptr, bp, hp, NPOL, 64, 1, 1);
    gemm_fp16_kernel<<<gS, 256>>>(xs16, w[11], nullptr, nullptr, bs, hs, NSTK, 64, 1, 1);
    // 6-7: finish CSR
    exscan2_kernel<<<2, 1024>>>(cnt_ps, NSTK, off_ps, cur_ps, cnt_sp, NPOL, off_sp, cur_sp);
    scatter2_kernel<<<400, 256>>>(eps_src, eps_dst, cur_ps, src_ps,
                                  esp_src, esp_dst, cur_sp, src_sp, EDG);
    // 8: fp16 copies of h (root operands for conv1)
    convert2_kernel<<<c2grid, 256>>>(hp, hp16, PROWS * HID, hs, hs16, SROWS * HID);

    // conv1
    agg_mean_kernel<<<NSTK, 128>>>(hp, off_ps, src_ps, means16);
    agg_mean_kernel<<<NPOL, 128>>>(hs, off_sp, src_sp, meanp16);
    gemm_fp16_kernel<<<gS, 256>>>(means16, w[0], hs16, w[1], c1_ps_bl, hs1, NSTK, 512, 2, 1);
    gemm_fp16_kernel<<<gP, 256>>>(meanp16, w[2], hp16, w[3], c1_sp_bl, hp1, NPOL, 512, 2, 1);
    convert2_kernel<<<c2grid, 256>>>(hs1, hs116, SROWS * HID, hp1, hp116, PROWS * HID);

    // conv2 (f32 outputs reuse g_hs/g_hp — originals dead)
    agg_mean_kernel<<<NSTK, 128>>>(hp1, off_ps, src_ps, means16);
    agg_mean_kernel<<<NPOL, 128>>>(hs1, off_sp, src_sp, meanp16);
    gemm_fp16_kernel<<<gS, 256>>>(means16, w[4], hs116, w[5], c2_ps_bl, hs, NSTK, 512, 2, 1);
    gemm_fp16_kernel<<<gP, 256>>>(meanp16, w[6], hp116, w[7], c2_sp_bl, hp, NPOL, 512, 2, 1);
    convert2_kernel<<<c2grid, 256>>>(hs, hs216, SROWS * HID, hp, hp216, PROWS * HID);

    // decoder factorization: A = hp2 @ d1_W[0:512], B = hs2 @ d1_W[512:1024]
    gemm_fp16_kernel<<<gP, 256>>>(hp216, w[8], nullptr, nullptr, nullptr, Abuf, NPOL, 512, 1, 0);
    gemm_fp16_kernel<<<gS, 256>>>(hs216, w[9], nullptr, nullptr, nullptr, Bbuf, NSTK, 512, 1, 0);

    // fused per-edge decoder
    edge_decode_kernel<<<2048, 256>>>(Abuf, Bbuf, attr,
                                      d1_W + (size_t)1024 * HID,
                                      d1_W + (size_t)1025 * HID,
                                      d1_b, d2_W, d2_b, trow, tcol, out);
}

// round 6
// speedup vs baseline: 2.4759x; 1.1728x over previous
#include <cuda_runtime.h>
#include <cuda_fp16.h>
#include <mma.h>
#include <cstdint>

using namespace nvcuda;

#define NPOL 20000
#define NSTK 10000
#define EDG  400000
#define HID  512
#define NC   3

// padded row counts (multiples of 128): no bounds checks in GEMM epilogues
#define PROWS 20096
#define SROWS 10112

#define WBIG (512 * 512)
#define WSML (64 * 512)

// ---------------- device scratch (fp16 activation buffers, reused across stages) ----
__device__ __half g_pA[(size_t)PROWS * HID];   // hp0 -> hp2
__device__ __half g_pB[(size_t)PROWS * HID];   // hp1 -> A
__device__ __half g_pC[(size_t)PROWS * HID];   // mean_sp(tmp)  (padded rows stay 0)
__device__ __half g_sA[(size_t)SROWS * HID];   // hs0 -> hs2
__device__ __half g_sB[(size_t)SROWS * HID];   // hs1 -> B
__device__ __half g_sC[(size_t)SROWS * HID];   // mean_ps
__device__ __half g_sD[(size_t)SROWS * HID];   // tmp (hs @ sp_Wl)

__device__ __half g_w16[10 * WBIG + 2 * WSML];
__device__ __half g_xp16[(size_t)NPOL * 64];
__device__ __half g_xs16[(size_t)NSTK * 64];

__device__ int g_cnt_ps[NSTK];
__device__ int g_off_ps[NSTK + 1];
__device__ int g_cur_ps[NSTK];
__device__ int g_src_ps[EDG];

__device__ int g_cnt_sp[NPOL];
__device__ int g_off_sp[NPOL + 1];
__device__ int g_cur_sp[NPOL];
__device__ int g_src_sp[EDG];

// ---------------- f32 -> f16 converts (weights + raw inputs) ----------------
struct CPack {
    const float* src[14];
    __half*      dst[14];
    int          cnt[14];
};

__global__ __launch_bounds__(256) void convert_all_kernel(CPack p) {
    int s = blockIdx.y;
    const float4* src = reinterpret_cast<const float4*>(p.src[s]);
    __half2* dst = reinterpret_cast<__half2*>(p.dst[s]);
    int n4 = p.cnt[s] >> 2;
    for (int i = blockIdx.x * blockDim.x + threadIdx.x; i < n4; i += gridDim.x * blockDim.x) {
        float4 v = src[i];
        dst[2 * i]     = __floats2half2_rn(v.x, v.y);
        dst[2 * i + 1] = __floats2half2_rn(v.z, v.w);
    }
}

// ---------------- CSR build ----------------
__global__ void zero2_kernel(int* a, int na, int* b, int nb) {
    int i  = blockIdx.x * blockDim.x + threadIdx.x;
    int st = gridDim.x * blockDim.x;
    for (int j = i; j < na; j += st) a[j] = 0;
    for (int j = i; j < nb; j += st) b[j] = 0;
}

__global__ void histo2_kernel(const int* __restrict__ d0, int* c0,
                              const int* __restrict__ d1, int* c1, int n) {
    int i  = blockIdx.x * blockDim.x + threadIdx.x;
    int st = gridDim.x * blockDim.x;
    for (int e = i; e < n; e += st) {
        atomicAdd(&c0[d0[e]], 1);
        atomicAdd(&c1[d1[e]], 1);
    }
}

__global__ __launch_bounds__(1024) void exscan2_kernel(
    const int* __restrict__ cnt0, int n0, int* off0, int* cur0,
    const int* __restrict__ cnt1, int n1, int* off1, int* cur1) {
    const int* cnt = blockIdx.x ? cnt1 : cnt0;
    int  n   = blockIdx.x ? n1 : n0;
    int* off = blockIdx.x ? off1 : off0;
    int* cur = blockIdx.x ? cur1 : cur0;

    __shared__ int buf[1024];
    __shared__ int s_carry;
    int tid = threadIdx.x;
    if (tid == 0) s_carry = 0;
    __syncthreads();

    for (int base = 0; base < n; base += 1024) {
        int i = base + tid;
        int v = (i < n) ? cnt[i] : 0;
        buf[tid] = v;
        __syncthreads();
        #pragma unroll
        for (int o = 1; o < 1024; o <<= 1) {
            int t = (tid >= o) ? buf[tid - o] : 0;
            __syncthreads();
            buf[tid] += t;
            __syncthreads();
        }
        int incl  = buf[tid];
        int total = buf[1023];
        if (i < n) {
            int ex = s_carry + incl - v;
            off[i] = ex;
            cur[i] = ex;
        }
        __syncthreads();
        if (tid == 0) s_carry += total;
        __syncthreads();
    }
    if (tid == 0) off[n] = s_carry;
}

__global__ void scatter2_kernel(const int* __restrict__ s0, const int* __restrict__ dd0,
                                int* cur0, int* o0,
                                const int* __restrict__ s1, const int* __restrict__ dd1,
                                int* cur1, int* o1, int n) {
    int i  = blockIdx.x * blockDim.x + threadIdx.x;
    int st = gridDim.x * blockDim.x;
    for (int e = i; e < n; e += st) {
        int p0 = atomicAdd(&cur0[dd0[e]], 1);
        o0[p0] = s0[e];
        int p1 = atomicAdd(&cur1[dd1[e]], 1);
        o1[p1] = s1[e];
    }
}

// ---------------- mean aggregation over CSR (fp16 in, fp32 accum, fp16 out) --------
__global__ __launch_bounds__(128) void agg_mean_kernel(
    const __half* __restrict__ X, const int* __restrict__ off,
    const int* __restrict__ srcs, __half* __restrict__ out) {
    int d   = blockIdx.x;
    int tid = threadIdx.x;
    int beg = off[d];
    int end = off[d + 1];

    __shared__ int sIdx[128];
    float a0 = 0.f, a1 = 0.f, a2 = 0.f, a3 = 0.f;

    for (int cb = beg; cb < end; cb += 128) {
        int m = min(128, end - cb);
        if (tid < m) sIdx[tid] = srcs[cb + tid];
        __syncthreads();
        for (int j = 0; j < m; j++) {
            const uint2* row = reinterpret_cast<const uint2*>(X + (size_t)sIdx[j] * HID);
            uint2 v = row[tid];
            float2 f0 = __half22float2(*reinterpret_cast<__half2*>(&v.x));
            float2 f1 = __half22float2(*reinterpret_cast<__half2*>(&v.y));
            a0 += f0.x; a1 += f0.y; a2 += f1.x; a3 += f1.y;
        }
        __syncthreads();
    }
    float inv = (end > beg) ? 1.0f / (float)(end - beg) : 0.0f;
    uint2 ov;
    *reinterpret_cast<__half2*>(&ov.x) = __floats2half2_rn(a0 * inv, a1 * inv);
    *reinterpret_cast<__half2*>(&ov.y) = __floats2half2_rn(a2 * inv, a3 * inv);
    reinterpret_cast<uint2*>(out + (size_t)d * HID)[tid] = ov;
}

// ---------------- cp.async helpers ----------------
__device__ __forceinline__ void cp_async16(void* dst, const void* src, bool pred) {
    uint32_t s = (uint32_t)__cvta_generic_to_shared(dst);
    int n = pred ? 16 : 0;
    asm volatile("cp.async.cg.shared.global [%0], [%1], 16, %2;\n" :: "r"(s), "l"(src), "r"(n));
}
__device__ __forceinline__ void cp_commit() { asm volatile("cp.async.commit_group;\n"); }
template <int N>
__device__ __forceinline__ void cp_wait() { asm volatile("cp.async.wait_group %0;\n" :: "n"(N)); }

// ---------------- fp16 WMMA GEMM, fp16 output ----------------
// C[M(pad),512](f16) = act( sum_p Xp @ Wp + bias + C0 )
// BM=128, BN=128, BK=32, 256 threads (8 warps; warp tile 32x64 = 2x4 m16n16k16)
#define XLDH 40
#define WLDH 136
#define SLDF 20   // staging ld (floats): 80 bytes, multiple of 16B as WMMA requires

__global__ __launch_bounds__(256) void gemm_fp16_kernel(
    const __half* __restrict__ X0, const __half* __restrict__ W0,
    const __half* __restrict__ X1, const __half* __restrict__ W1,
    const float* __restrict__ bias, const __half* __restrict__ C0,
    __half* __restrict__ C,
    int M, int K, int npair, int dorelu) {
    __shared__ __half Xs[2][128][XLDH];
    __shared__ __half Ws[2][32][WLDH];
    __shared__ float s_bias[128];
    __shared__ __align__(16) float stage[8][16 * SLDF];  // per-warp 16x16 f32 staging

    const int row0 = blockIdx.x * 128;
    const int n0   = blockIdx.y * 128;
    const int tid  = threadIdx.x;
    const int warp = tid >> 5;
    const int lane = tid & 31;
    const int wm   = warp >> 1;   // 0..3
    const int wn   = warp & 1;    // 0..1

    if (tid < 128) s_bias[tid] = bias ? bias[n0 + tid] : 0.0f;

    wmma::fragment<wmma::accumulator, 16, 16, 16, float> acc[2][4];
    #pragma unroll
    for (int i = 0; i < 2; i++)
        #pragma unroll
        for (int j = 0; j < 4; j++)
            wmma::fill_fragment(acc[i][j], 0.0f);

    const int CK = K >> 5;
    const int T  = npair * CK;

    auto load_chunk = [&](int c, int buf) {
        int pair = (c >= CK) ? 1 : 0;
        const __half* X = pair ? X1 : X0;
        const __half* W = pair ? W1 : W0;
        int kk = (c - pair * CK) * 32;
        #pragma unroll
        for (int q = 0; q < 2; q++) {
            int u = tid + q * 256;
            int r = u >> 2, cu = u & 3;
            int rg = row0 + r;
            cp_async16(&Xs[buf][r][cu * 8], X + (size_t)rg * K + kk + cu * 8, rg < M);
        }
        #pragma unroll
        for (int q = 0; q < 2; q++) {
            int u = tid + q * 256;
            int r = u >> 4, cu = u & 15;
            cp_async16(&Ws[buf][r][cu * 8], W + (size_t)(kk + r) * HID + n0 + cu * 8, true);
        }
        cp_commit();
    };

    auto compute = [&](int buf) {
        #pragma unroll
        for (int kk = 0; kk < 32; kk += 16) {
            wmma::fragment<wmma::matrix_a, 16, 16, 16, __half, wmma::row_major> a[2];
            wmma::fragment<wmma::matrix_b, 16, 16, 16, __half, wmma::row_major> b[4];
            #pragma unroll
            for (int i = 0; i < 2; i++)
                wmma::load_matrix_sync(a[i], &Xs[buf][wm * 32 + i * 16][kk], XLDH);
            #pragma unroll
            for (int j = 0; j < 4; j++)
                wmma::load_matrix_sync(b[j], &Ws[buf][kk][wn * 64 + j * 16], WLDH);
            #pragma unroll
            for (int i = 0; i < 2; i++)
                #pragma unroll
                for (int j = 0; j < 4; j++)
                    wmma::mma_sync(acc[i][j], a[i], b[j], acc[i][j]);
        }
    };

    load_chunk(0, 0);
    int buf = 0;
    for (int t = 0; t < T; t++) {
        if (t + 1 < T) load_chunk(t + 1, buf ^ 1);
        if (t + 1 < T) cp_wait<1>(); else cp_wait<0>();
        __syncthreads();
        compute(buf);
        __syncthreads();
        buf ^= 1;
    }

    // epilogue: stage each 16x16 frag in smem (f32), add bias/C0, relu, store half8
    const int lr = lane >> 1;
    const int lc = (lane & 1) * 8;
    #pragma unroll
    for (int i = 0; i < 2; i++) {
        #pragma unroll
        for (int j = 0; j < 4; j++) {
            wmma::store_matrix_sync(&stage[warp][0], acc[i][j], SLDF, wmma::mem_row_major);
            __syncwarp();
            int grow = row0 + wm * 32 + i * 16 + lr;
            int bcol = wn * 64 + j * 16 + lc;
            const float* sp = &stage[warp][lr * SLDF + lc];
            float v[8];
            #pragma unroll
            for (int t = 0; t < 8; t++) v[t] = sp[t] + s_bias[bcol + t];
            if (C0) {
                uint4 cz = *reinterpret_cast<const uint4*>(C0 + (size_t)grow * HID + n0 + bcol);
                float2 c0 = __half22float2(*reinterpret_cast<__half2*>(&cz.x));
                float2 c1 = __half22float2(*reinterpret_cast<__half2*>(&cz.y));
                float2 c2 = __half22float2(*reinterpret_cast<__half2*>(&cz.z));
                float2 c3 = __half22float2(*reinterpret_cast<__half2*>(&cz.w));
                v[0] += c0.x; v[1] += c0.y; v[2] += c1.x; v[3] += c1.y;
                v[4] += c2.x; v[5] += c2.y; v[6] += c3.x; v[7] += c3.y;
            }
            if (dorelu) {
                #pragma unroll
                for (int t = 0; t < 8; t++) v[t] = fmaxf(v[t], 0.0f);
            }
            uint4 ov;
            *reinterpret_cast<__half2*>(&ov.x) = __floats2half2_rn(v[0], v[1]);
            *reinterpret_cast<__half2*>(&ov.y) = __floats2half2_rn(v[2], v[3]);
            *reinterpret_cast<__half2*>(&ov.z) = __floats2half2_rn(v[4], v[5]);
            *reinterpret_cast<__half2*>(&ov.w) = __floats2half2_rn(v[6], v[7]);
            *reinterpret_cast<uint4*>(C + (size_t)grow * HID + n0 + bcol) = ov;
            __syncwarp();
        }
    }
}

// ---------------- fused per-edge decoder (fp16 A/B, fp32 math) ----------------
__global__ __launch_bounds__(256) void edge_decode_kernel(
    const __half* __restrict__ Aa, const __half* __restrict__ Bb,
    const float* __restrict__ attr,
    const float* __restrict__ w0, const float* __restrict__ w1,
    const float* __restrict__ b1,
    const float* __restrict__ d2W, const float* __restrict__ d2b,
    const int* __restrict__ erow, const int* __restrict__ ecol,
    float* __restrict__ out) {
    __shared__ float4 s_w0[128], s_w1[128], s_b[128], s_d0[128], s_d1[128], s_d2[128];
    int tid = threadIdx.x;
    for (int i = tid; i < HID; i += 256) {
        ((float*)s_w0)[i] = w0[i];
        ((float*)s_w1)[i] = w1[i];
        ((float*)s_b)[i]  = b1[i];
        ((float*)s_d0)[i] = d2W[i * 3 + 0];
        ((float*)s_d1)[i] = d2W[i * 3 + 1];
        ((float*)s_d2)[i] = d2W[i * 3 + 2];
    }
    __syncthreads();
    float db0 = d2b[0], db1 = d2b[1], db2 = d2b[2];
    int lane = tid & 31;
    int warp = tid >> 5;

    for (int e = blockIdx.x * 8 + warp; e < EDG; e += gridDim.x * 8) {
        int r = erow[e];
        int c = ecol[e];
        float a0 = attr[2 * e];
        float a1 = attr[2 * e + 1];
        const uint2* A4 = reinterpret_cast<const uint2*>(Aa + (size_t)r * HID);
        const uint2* B4 = reinterpret_cast<const uint2*>(Bb + (size_t)c * HID);
        float s0 = 0.f, s1 = 0.f, s2 = 0.f;
        #pragma unroll
        for (int k = 0; k < 4; k++) {
            int q = k * 32 + lane;
            uint2 au = A4[q], bu = B4[q];
            float2 a01 = __half22float2(*reinterpret_cast<__half2*>(&au.x));
            float2 a23 = __half22float2(*reinterpret_cast<__half2*>(&au.y));
            float2 b01 = __half22float2(*reinterpret_cast<__half2*>(&bu.x));
            float2 b23 = __half22float2(*reinterpret_cast<__half2*>(&bu.y));
            float4 va = make_float4(a01.x, a01.y, a23.x, a23.y);
            float4 vb = make_float4(b01.x, b01.y, b23.x, b23.y);
            float4 vw0 = s_w0[q], vw1 = s_w1[q], vbb = s_b[q];
            float4 v0 = s_d0[q], v1 = s_d1[q], v2 = s_d2[q];
            float h;
            h = fmaxf(va.x + vb.x + a0 * vw0.x + a1 * vw1.x + vbb.x, 0.f);
            s0 += h * v0.x; s1 += h * v1.x; s2 += h * v2.x;
            h = fmaxf(va.y + vb.y + a0 * vw0.y + a1 * vw1.y + vbb.y, 0.f);
            s0 += h * v0.y; s1 += h * v1.y; s2 += h * v2.y;
            h = fmaxf(va.z + vb.z + a0 * vw0.z + a1 * vw1.z + vbb.z, 0.f);
            s0 += h * v0.z; s1 += h * v1.z; s2 += h * v2.z;
            h = fmaxf(va.w + vb.w + a0 * vw0.w + a1 * vw1.w + vbb.w, 0.f);
            s0 += h * v0.w; s1 += h * v1.w; s2 += h * v2.w;
        }
        #pragma unroll
        for (int o = 16; o > 0; o >>= 1) {
            s0 += __shfl_xor_sync(0xffffffffu, s0, o);
            s1 += __shfl_xor_sync(0xffffffffu, s1, o);
            s2 += __shfl_xor_sync(0xffffffffu, s2, o);
        }
        if (lane == 0) {
            out[(size_t)e * 3 + 0] = s0 + db0;
            out[(size_t)e * 3 + 1] = s1 + db1;
            out[(size_t)e * 3 + 2] = s2 + db2;
        }
    }
}

// ---------------- host launch ----------------
extern "C" void kernel_launch(void* const* d_in, const int* in_sizes, int n_in,
                              void* d_out, int out_size) {
    (void)in_sizes; (void)n_in; (void)out_size;

    const float* x_pol = (const float*)d_in[0];
    const float* x_stk = (const float*)d_in[1];
    const float* attr  = (const float*)d_in[2];
    const float* Wp    = (const float*)d_in[3];
    const float* bp    = (const float*)d_in[4];
    const float* Ws    = (const float*)d_in[5];
    const float* bs    = (const float*)d_in[6];
    const float* c1_ps_Wl = (const float*)d_in[7];
    const float* c1_ps_bl = (const float*)d_in[8];
    const float* c1_ps_Wr = (const float*)d_in[9];
    const float* c1_sp_Wl = (const float*)d_in[10];
    const float* c1_sp_bl = (const float*)d_in[11];
    const float* c1_sp_Wr = (const float*)d_in[12];
    const float* c2_ps_Wl = (const float*)d_in[13];
    const float* c2_ps_bl = (const float*)d_in[14];
    const float* c2_ps_Wr = (const float*)d_in[15];
    const float* c2_sp_Wl = (const float*)d_in[16];
    const float* c2_sp_bl = (const float*)d_in[17];
    const float* c2_sp_Wr = (const float*)d_in[18];
    const float* d1_W  = (const float*)d_in[19];   // [1026, 512]
    const float* d1_b  = (const float*)d_in[20];
    const float* d2_W  = (const float*)d_in[21];   // [512, 3]
    const float* d2_b  = (const float*)d_in[22];
    const int* eps_src = (const int*)d_in[23];
    const int* eps_dst = (const int*)d_in[24];
    const int* esp_src = (const int*)d_in[25];
    const int* esp_dst = (const int*)d_in[26];
    const int* trow    = (const int*)d_in[27];
    const int* tcol    = (const int*)d_in[28];
    float* out = (float*)d_out;

    void* p;
    cudaGetSymbolAddress(&p, g_pA);     __half* pA = (__half*)p;
    cudaGetSymbolAddress(&p, g_pB);     __half* pB = (__half*)p;
    cudaGetSymbolAddress(&p, g_pC);     __half* pC = (__half*)p;
    cudaGetSymbolAddress(&p, g_sA);     __half* sA = (__half*)p;
    cudaGetSymbolAddress(&p, g_sB);     __half* sB = (__half*)p;
    cudaGetSymbolAddress(&p, g_sC);     __half* sC = (__half*)p;
    cudaGetSymbolAddress(&p, g_sD);     __half* sD = (__half*)p;
    cudaGetSymbolAddress(&p, g_w16);    __half* w16 = (__half*)p;
    cudaGetSymbolAddress(&p, g_xp16);   __half* xp16 = (__half*)p;
    cudaGetSymbolAddress(&p, g_xs16);   __half* xs16 = (__half*)p;
    cudaGetSymbolAddress(&p, g_cnt_ps); int* cnt_ps = (int*)p;
    cudaGetSymbolAddress(&p, g_off_ps); int* off_ps = (int*)p;
    cudaGetSymbolAddress(&p, g_cur_ps); int* cur_ps = (int*)p;
    cudaGetSymbolAddress(&p, g_src_ps); int* src_ps = (int*)p;
    cudaGetSymbolAddress(&p, g_cnt_sp); int* cnt_sp = (int*)p;
    cudaGetSymbolAddress(&p, g_off_sp); int* off_sp = (int*)p;
    cudaGetSymbolAddress(&p, g_cur_sp); int* cur_sp = (int*)p;
    cudaGetSymbolAddress(&p, g_src_sp); int* src_sp = (int*)p;

    // fp16 weight table
    __half* w[12];
    const float* wsrc[12] = {c1_ps_Wl, c1_ps_Wr, c1_sp_Wl, c1_sp_Wr,
                             c2_ps_Wl, c2_ps_Wr, c2_sp_Wl, c2_sp_Wr,
                             d1_W, d1_W + (size_t)512 * HID, Wp, Ws};
    for (int i = 0; i < 10; i++) w[i] = w16 + (size_t)i * WBIG;
    w[10] = w16 + (size_t)10 * WBIG;
    w[11] = w16 + (size_t)10 * WBIG + WSML;

    CPack cp;
    for (int i = 0; i < 12; i++) { cp.src[i] = wsrc[i]; cp.dst[i] = w[i]; cp.cnt[i] = (i < 10) ? WBIG : WSML; }
    cp.src[12] = x_pol; cp.dst[12] = xp16; cp.cnt[12] = NPOL * 64;
    cp.src[13] = x_stk; cp.dst[13] = xs16; cp.cnt[13] = NSTK * 64;

    dim3 gP(PROWS / 128, 4);
    dim3 gS(SROWS / 128, 4);

    // converts + CSR front
    convert_all_kernel<<<dim3(256, 14), 256>>>(cp);
    zero2_kernel<<<64, 256>>>(cnt_ps, NSTK, cnt_sp, NPOL);
    histo2_kernel<<<400, 256>>>(eps_dst, cnt_ps, esp_dst, cnt_sp, EDG);

    // projections (fp16 out)
    gemm_fp16_kernel<<<gP, 256>>>(xp16, w[10], nullptr, nullptr, bp, nullptr, pA, NPOL, 64, 1, 1);
    gemm_fp16_kernel<<<gS, 256>>>(xs16, w[11], nullptr, nullptr, bs, nullptr, sA, NSTK, 64, 1, 1);

    // finish CSR
    exscan2_kernel<<<2, 1024>>>(cnt_ps, NSTK, off_ps, cur_ps, cnt_sp, NPOL, off_sp, cur_sp);
    scatter2_kernel<<<400, 256>>>(eps_src, eps_dst, cur_ps, src_ps,
                                  esp_src, esp_dst, cur_sp, src_sp, EDG);

    // ---- layer 1 ----
    // sp transform-first: tmp = hs @ c1_sp_Wl (10k rows), then aggregate
    gemm_fp16_kernel<<<gS, 256>>>(sA, w[2], nullptr, nullptr, nullptr, nullptr, sD, NSTK, 512, 1, 0);
    agg_mean_kernel<<<NSTK, 128>>>(pA, off_ps, src_ps, sC);   // mean_ps(hp)
    agg_mean_kernel<<<NPOL, 128>>>(sD, off_sp, src_sp, pC);   // mean_sp(tmp)
    // hs1 = relu(mean_ps @ Wl + hs @ Wr + bl)
    gemm_fp16_kernel<<<gS, 256>>>(sC, w[0], sA, w[1], c1_ps_bl, nullptr, sB, NSTK, 512, 2, 1);
    // hp1 = relu(C0(=mean_sp(tmp)) + hp @ Wr + bl)
    gemm_fp16_kernel<<<gP, 256>>>(pA, w[3], nullptr, nullptr, c1_sp_bl, pC, pB, NPOL, 512, 1, 1);

    // ---- layer 2 ----
    gemm_fp16_kernel<<<gS, 256>>>(sB, w[6], nullptr, nullptr, nullptr, nullptr, sD, NSTK, 512, 1, 0);
    agg_mean_kernel<<<NSTK, 128>>>(pB, off_ps, src_ps, sC);
    agg_mean_kernel<<<NPOL, 128>>>(sD, off_sp, src_sp, pC);
    gemm_fp16_kernel<<<gS, 256>>>(sC, w[4], sB, w[5], c2_ps_bl, nullptr, sA, NSTK, 512, 2, 1);
    gemm_fp16_kernel<<<gP, 256>>>(pB, w[7], nullptr, nullptr, c2_sp_bl, pC, pA, NPOL, 512, 1, 1);

    // ---- decoder factorization ----
    gemm_fp16_kernel<<<gP, 256>>>(pA, w[8], nullptr, nullptr, nullptr, nullptr, pB, NPOL, 512, 1, 0);
    gemm_fp16_kernel<<<gS, 256>>>(sA, w[9], nullptr, nullptr, nullptr, nullptr, sB, NSTK, 512, 1, 0);

    // ---- fused per-edge decoder ----
    edge_decode_kernel<<<2048, 256>>>(pB, sB, attr,
                                      d1_W + (size_t)1024 * HID,
                                      d1_W + (size_t)1025 * HID,
                                      d1_b, d2_W, d2_b, trow, tcol, out);
}